// round 8
// baseline (speedup 1.0000x reference)
#include <cuda_runtime.h>
#include <cuda_fp16.h>

// Concordance index via fp16 counting sort of y.
//   key = order-preserving u16 of fp16(y); sort all elements by key.
//   For event a: s_a = #{elements with key <= key_a} (suffix start).
//     tp_a = N - s_a                               (analytic, no loop)
//     cc_a = #{ j in [s_a, N) : h_sorted[j] >= h_a }   (2 ops / 2 pairs)
// Pair predicates identical to the previous fp16 kernel -> same result.
// One persistent kernel, 5 spin grid barriers, deterministic integer sums.

#define THREADS 256
#define GRID    592                  // 148 SMs x 4 blocks, single wave
#define MAXN    16384
#define NBINS   65536
#define ROWS_R  2
#define CE      (THREADS * ROWS_R)   // 512 events per pair-chunk
#define TJ      256                  // j-tile staged in smem

__device__ unsigned long long g_acc;          // hi 32: cc, lo 32: tp
__device__ unsigned int   g_hist[NBINS];      // zero at load; re-zeroed each run
__device__ unsigned int   g_cnt [NBINS];      // scatter counters; same
__device__ unsigned int   g_pref[NBINS];      // within-chunk exclusive prefix
__device__ unsigned int   g_ctot[256];        // per-256-bin-chunk totals
__device__ unsigned int   g_rec [MAXN];       // key<<16 | h_bits
__device__ unsigned short g_skey[MAXN];       // sorted keys
__device__ unsigned short g_shh [MAXN];       // sorted h (fp16 bits)
__device__ unsigned char  g_sst [MAXN];       // sorted status flags
__device__ unsigned int   g_evs [MAXN];       // event suffix starts (y-sorted)
__device__ unsigned short g_evh [MAXN];       // event h (fp16 bits)
__device__ unsigned int   g_evcnt[64];        // events per 256-position chunk
__device__ int            g_nev;
__device__ unsigned int   g_bar[5];           // grid-barrier counters
__device__ unsigned int   g_done2;            // final arrival counter

__device__ __forceinline__ void gbar(int i) {
    __syncthreads();
    if (threadIdx.x == 0) {
        __threadfence();
        atomicAdd(&g_bar[i], 1u);
        while (*((volatile unsigned int*)&g_bar[i]) < GRID) __nanosleep(32);
    }
    __syncthreads();
}

// order-preserving u16 key of fp16(v)
__device__ __forceinline__ unsigned short f2key(float v) {
    unsigned short b = __half_as_ushort(__float2half_rn(v));
    return (b & 0x8000u) ? (unsigned short)(~b) : (unsigned short)(b | 0x8000u);
}

// inclusive Hillis-Steele scan over THREADS values in s (leaves inclusive sums)
#define ISCAN(s, val) {                                              \
    (s)[t] = (val); __syncthreads();                                 \
    for (int _o = 1; _o < THREADS; _o <<= 1) {                       \
        unsigned _x = (t >= _o) ? (s)[t - _o] : 0u;                  \
        __syncthreads(); (s)[t] += _x; __syncthreads();              \
    } }

__global__ __launch_bounds__(THREADS, 4) void cindex_sort_kernel(
    const float* __restrict__ y,
    const float* __restrict__ h,
    const int*   __restrict__ st,
    float* __restrict__ out,
    int n)
{
    __shared__ unsigned int s_scan[THREADS];
    __shared__ unsigned int s_coff[256];
    __shared__ unsigned int s_h32[TJ / 2];
    __shared__ unsigned int s_red[THREADS / 32];

    const int t   = threadIdx.x;
    const int blk = blockIdx.x;
    const int gid = blk * THREADS + t;
    const int nb  = (n + THREADS - 1) / THREADS;   // 64 data blocks

    // ---- Ph0: pack records + key histogram --------------------------------
    if (gid < n) {
        unsigned short ky = f2key(y[gid]);
        unsigned short hb = __half_as_ushort(__float2half_rn(h[gid]));
        g_rec[gid] = ((unsigned)ky << 16) | (unsigned)hb;
        atomicAdd(&g_hist[ky], 1u);
    }
    gbar(0);

    // ---- Ph1: 256 blocks scan their 256 bins ------------------------------
    if (blk < 256) {
        unsigned v = g_hist[blk * 256 + t];
        ISCAN(s_scan, v);
        g_pref[blk * 256 + t] = s_scan[t] - v;       // exclusive within chunk
        if (t == THREADS - 1) g_ctot[blk] = s_scan[t];
    }
    gbar(1);

    // ---- Ph2: scatter into sorted order (first nb blocks) -----------------
    if (blk < nb) {
        unsigned v = g_ctot[t];
        ISCAN(s_scan, v);
        s_coff[t] = s_scan[t] - v;                   // chunk offsets
        __syncthreads();
        if (gid < n) {
            unsigned rec = g_rec[gid];
            unsigned key = rec >> 16;
            unsigned pos = g_pref[key] + s_coff[key >> 8] + atomicAdd(&g_cnt[key], 1u);
            g_skey[pos] = (unsigned short)key;
            g_shh [pos] = (unsigned short)(rec & 0xFFFFu);
            g_sst [pos] = (unsigned char)(st[gid] == 1);
        }
    }
    gbar(2);

    // ---- Ph3: per-256-position event counts (blocks < nb) -----------------
    if (blk < nb) {
        int p = blk * 256 + t;
        unsigned f = (p < n) ? (unsigned)g_sst[p] : 0u;
        unsigned c = f;
#pragma unroll
        for (int o = 16; o > 0; o >>= 1) c += __shfl_down_sync(0xFFFFFFFFu, c, o);
        if ((t & 31) == 0) s_red[t >> 5] = c;
        __syncthreads();
        if (t == 0) {
            unsigned bs = 0;
#pragma unroll
            for (int i = 0; i < THREADS / 32; i++) bs += s_red[i];
            g_evcnt[blk] = bs;
        }
    }
    gbar(3);

    // ---- Ph4: ordered event extraction + suffix starts + tp ---------------
    if (blk < nb) {
        unsigned v = g_ctot[t];
        ISCAN(s_scan, v);
        s_coff[t] = s_scan[t] - v;
        __syncthreads();
        unsigned v2 = (t < nb) ? g_evcnt[t] : 0u;
        ISCAN(s_scan, v2);
        unsigned eoff = (blk == 0) ? 0u : s_scan[blk - 1];
        unsigned tot  = s_scan[THREADS - 1];
        if (blk == 0 && t == 0) g_nev = (int)tot;
        __syncthreads();

        int p = blk * 256 + t;
        unsigned f = (p < n) ? (unsigned)g_sst[p] : 0u;
        ISCAN(s_scan, f);
        unsigned rank = s_scan[t] - f;               // exclusive rank in block
        unsigned tp32 = 0u;
        if (f) {
            unsigned key = (unsigned)g_skey[p];
            unsigned s = g_pref[key] + s_coff[key >> 8] + g_cnt[key];  // suffix start
            unsigned e = eoff + rank;
            g_evs[e] = s;
            g_evh[e] = g_shh[p];
            tp32 = (unsigned)(n - (int)s);
        }
#pragma unroll
        for (int o = 16; o > 0; o >>= 1) tp32 += __shfl_down_sync(0xFFFFFFFFu, tp32, o);
        if ((t & 31) == 0) s_red[t >> 5] = tp32;
        __syncthreads();
        if (t == 0) {
            unsigned bs = 0;
#pragma unroll
            for (int i = 0; i < THREADS / 32; i++) bs += s_red[i];
            if (bs) atomicAdd(&g_acc, (unsigned long long)bs);   // tp in low 32
        }
    }
    gbar(4);

    // ---- Ph5: suffix pair phase -------------------------------------------
    const int nev     = *((volatile int*)&g_nev);
    const int nchunks = (nev + CE - 1) / CE;
    unsigned int cc = 0u;

    // full tiles: chunk ch covers j in [T, n), T = max suffix start in chunk
    for (int w = blk; w < nchunks * 64; w += GRID) {
        const int ch = w >> 6, k = w & 63;
        const int elast = min(ch * CE + CE, nev) - 1;
        const int T  = (int)g_evs[elast];
        const int j0 = T + k * TJ;
        if (j0 >= n) continue;                        // uniform per block

        __syncthreads();                              // protect s_h32 reuse
        int j = j0 + t;
        ((unsigned short*)s_h32)[t] = (j < n) ? g_shh[j] : (unsigned short)0xFC00u; // -inf
        __syncthreads();

        __half2 ha2[ROWS_R], cc2[ROWS_R];
#pragma unroll
        for (int r = 0; r < ROWS_R; r++) {
            int e = ch * CE + t + r * THREADS;
            unsigned short hb = (e < nev) ? g_evh[e] : (unsigned short)0x7C00u;     // +inf
            ha2[r] = __half2half2(__ushort_as_half(hb));
            cc2[r] = __float2half2_rn(0.0f);
        }
        const __half2* sp = (const __half2*)s_h32;
#pragma unroll 8
        for (int jj = 0; jj < TJ / 2; jj++) {
            __half2 hb2 = sp[jj];
#pragma unroll
            for (int r = 0; r < ROWS_R; r++)
                cc2[r] = __hadd2(cc2[r], __hge2(hb2, ha2[r]));    // count h_b >= h_a
        }
        float cf = 0.0f;
#pragma unroll
        for (int r = 0; r < ROWS_R; r++)
            cf += __low2float(cc2[r]) + __high2float(cc2[r]);     // <=128/half: exact
        cc += (unsigned int)cf;
    }

    // boundary slivers: event e covers j in [s_e, T_chunk), one warp per event
    {
        const int nw = THREADS / 32;
        const int gw = blk * nw + (t >> 5), lane = t & 31;
        for (int e = gw; e < nev; e += GRID * nw) {
            const int ch = e / CE;
            const int elast = min(ch * CE + CE, nev) - 1;
            const int T  = (int)g_evs[elast];
            const int s0 = (int)g_evs[e];
            const __half ha = __ushort_as_half(g_evh[e]);
            unsigned c = 0u;
            for (int j = s0 + lane; j < T; j += 32)
                if (__hge(__ushort_as_half(g_shh[j]), ha)) c++;
#pragma unroll
            for (int o = 16; o > 0; o >>= 1) c += __shfl_down_sync(0xFFFFFFFFu, c, o);
            if (lane == 0) cc += c;
        }
    }

    // zero-chores for next graph replay (hist/cnt no longer read this run)
    for (int i = gid; i < NBINS; i += GRID * THREADS) { g_hist[i] = 0u; g_cnt[i] = 0u; }

    // ---- block reduce cc + arrival / finalize -----------------------------
#pragma unroll
    for (int o = 16; o > 0; o >>= 1) cc += __shfl_down_sync(0xFFFFFFFFu, cc, o);
    if ((t & 31) == 0) s_red[t >> 5] = cc;
    __syncthreads();
    if (t == 0) {
        unsigned bc = 0u;
#pragma unroll
        for (int i = 0; i < THREADS / 32; i++) bc += s_red[i];
        if (bc) atomicAdd(&g_acc, ((unsigned long long)bc) << 32);
        __threadfence();
        unsigned a = atomicAdd(&g_done2, 1u) + 1u;
        if (a == GRID) {                             // all blocks fully done
            unsigned long long acc = *((volatile unsigned long long*)&g_acc);
            out[0] = (float)(unsigned)(acc >> 32) / (float)(unsigned)(acc & 0xFFFFFFFFull);
            g_acc = 0ull; g_done2 = 0u; g_nev = 0;
#pragma unroll
            for (int i = 0; i < 5; i++) g_bar[i] = 0u;
        }
    }
}

extern "C" void kernel_launch(void* const* d_in, const int* in_sizes, int n_in,
                              void* d_out, int out_size) {
    const float* y  = (const float*)d_in[0];
    const float* yh = (const float*)d_in[1];
    const int*   st = (const int*)d_in[2];
    float* out = (float*)d_out;

    int n = in_sizes[0];  // 16384
    cindex_sort_kernel<<<GRID, THREADS>>>(y, yh, st, out, n);
}

// round 10
// speedup vs baseline: 1.2675x; 1.2675x over previous
#include <cuda_runtime.h>
#include <cuda_fp16.h>

// Concordance index via fp16 counting sort of y (lean-infrastructure version).
//   key = order-preserving u16 of fp16(y).
//   s_a = #{keys <= key_a}:  tp_a = N - s_a (analytic)
//   cc_a = #{ j in [s_a, N) : h_sorted[j] >= h_a }  (1 instr/pair, ~N^2/8 pairs)
// Packed dual histogram (lo16=all, hi16=events) -> one scan gives both
// prefixes; packed scatter atomic returns both ranks. 3 grid barriers total.

#define THREADS 256
#define GRID    592                 // 148 SMs x 4 blocks, single wave
#define MAXN    16384
#define NBINS   65536
#define ROWS_R  2
#define CE      (THREADS * ROWS_R)  // 512 events per pair-chunk
#define TJ      256                 // j-tile staged in smem

__device__ unsigned long long g_acc;        // hi 32: cc, lo 32: tp
__device__ unsigned int   g_hist[NBINS];    // packed (ev<<16)|all counts
__device__ unsigned int   g_cnt [NBINS];    // packed scatter rank counters
__device__ unsigned int   g_pref[NBINS];    // packed exclusive prefix (in-chunk)
__device__ unsigned int   g_ctot[256];      // packed chunk totals
__device__ unsigned int   g_rec [MAXN];     // key<<16 | h_bits
__device__ unsigned short g_shh [MAXN];     // h sorted by y
__device__ unsigned int   g_evs [MAXN];     // event suffix starts (y-ordered)
__device__ unsigned short g_evh [MAXN];     // event h bits (y-ordered)
__device__ int            g_nev;
__device__ unsigned int   g_bar[3];
__device__ unsigned int   g_done2;

__device__ __forceinline__ void gbar(int i) {
    __syncthreads();
    if (threadIdx.x == 0) {
        __threadfence();
        atomicAdd(&g_bar[i], 1u);
        while (*((volatile unsigned int*)&g_bar[i]) < GRID) __nanosleep(20);
    }
    __syncthreads();
}

__device__ __forceinline__ unsigned short f2key(float v) {
    unsigned short b = __half_as_ushort(__float2half_rn(v));
    return (b & 0x8000u) ? (unsigned short)(~b) : (unsigned short)(b | 0x8000u);
}

__device__ __forceinline__ unsigned wscan(unsigned v, int lane) {
#pragma unroll
    for (int o = 1; o < 32; o <<= 1) {
        unsigned x = __shfl_up_sync(0xFFFFFFFFu, v, o);
        if (lane >= o) v += x;
    }
    return v;   // inclusive
}

// inclusive scan of 256 values (one per thread); also returns grand total
__device__ __forceinline__ unsigned bscan256(unsigned v, int t,
                                             unsigned* s_wt, unsigned* total) {
    const int lane = t & 31, w = t >> 5;
    unsigned x = wscan(v, lane);
    if (lane == 31) s_wt[w] = x;
    __syncthreads();
    if (t < 32) {
        unsigned tv = (t < 8) ? s_wt[t] : 0u;
        tv = wscan(tv, t);
        if (t < 8) s_wt[t] = tv;
    }
    __syncthreads();
    unsigned incl = x + ((w > 0) ? s_wt[w - 1] : 0u);
    *total = s_wt[7];
    return incl;
}

__global__ __launch_bounds__(THREADS, 4) void cindex_sort2_kernel(
    const float* __restrict__ y,
    const float* __restrict__ h,
    const int*   __restrict__ st,
    float* __restrict__ out,
    int n)
{
    __shared__ unsigned int s_wt[8];
    __shared__ unsigned int s_coff[256];
    __shared__ unsigned int s_h32[TJ / 2];
    __shared__ unsigned int s_red[THREADS / 32];

    const int t   = threadIdx.x;
    const int blk = blockIdx.x;
    const int gid = blk * THREADS + t;
    const int nb  = (n + THREADS - 1) / THREADS;   // 64 data blocks

    // ---- Ph0: pack records + packed dual histogram ------------------------
    if (gid < n) {
        unsigned short ky = f2key(y[gid]);
        unsigned short hb = __half_as_ushort(__float2half_rn(h[gid]));
        g_rec[gid] = ((unsigned)ky << 16) | (unsigned)hb;
        atomicAdd(&g_hist[ky], (st[gid] == 1) ? 0x10001u : 1u);
    }
    gbar(0);

    // ---- Ph1: 256 blocks scan their 256 bins (packed) ---------------------
    if (blk < 256) {
        unsigned v = g_hist[blk * 256 + t];
        unsigned tot;
        unsigned incl = bscan256(v, t, s_wt, &tot);
        g_pref[blk * 256 + t] = incl - v;          // packed exclusive in-chunk
        if (t == 0) g_ctot[blk] = tot;
    }
    gbar(1);

    // ---- Ph2: scatter + event extraction + tp (blocks < nb) ---------------
    if (blk < nb) {
        unsigned v = g_ctot[t];
        unsigned tot;
        unsigned incl = bscan256(v, t, s_wt, &tot);
        s_coff[t] = incl - v;                       // packed chunk offsets
        if (blk == 0 && t == 0) g_nev = (int)(tot >> 16);
        __syncthreads();

        unsigned tp32 = 0u;
        {
            unsigned rec = g_rec[gid];
            unsigned key = rec >> 16;
            bool ev = (st[gid] == 1);
            unsigned ret = atomicAdd(&g_cnt[key], ev ? 0x10001u : 1u);
            unsigned pe  = g_pref[key] + s_coff[key >> 8];      // packed excl
            unsigned pos = (pe & 0xFFFFu) + (ret & 0xFFFFu);
            g_shh[pos] = (unsigned short)(rec & 0xFFFFu);
            if (ev) {
                unsigned s    = (pe & 0xFFFFu) + (g_hist[key] & 0xFFFFu);
                unsigned eidx = (pe >> 16) + (ret >> 16);
                g_evs[eidx] = s;
                g_evh[eidx] = (unsigned short)(rec & 0xFFFFu);
                tp32 = (unsigned)(n - (int)s);
            }
        }
#pragma unroll
        for (int o = 16; o > 0; o >>= 1) tp32 += __shfl_down_sync(0xFFFFFFFFu, tp32, o);
        if ((t & 31) == 0) s_red[t >> 5] = tp32;
        __syncthreads();
        if (t == 0) {
            unsigned bs = 0;
#pragma unroll
            for (int i = 0; i < THREADS / 32; i++) bs += s_red[i];
            if (bs) atomicAdd(&g_acc, (unsigned long long)bs);  // tp in low 32
        }
    }
    gbar(2);

    // ---- Ph3: suffix pair phase -------------------------------------------
    const int nev     = *((volatile int*)&g_nev);
    const int nchunks = (nev + CE - 1) / CE;
    unsigned int cc = 0u;

    // full tiles: chunk ch covers j in [T, n), T = suffix start of last event
    for (int w = blk; w < nchunks * 64; w += GRID) {
        const int ch = w >> 6, k = w & 63;
        const int elast = min(ch * CE + CE, nev) - 1;
        const int T  = (int)g_evs[elast];
        const int j0 = T + k * TJ;
        if (j0 >= n) continue;                      // uniform per block

        __syncthreads();                            // protect s_h32 reuse
        int j = j0 + t;
        ((unsigned short*)s_h32)[t] = (j < n) ? g_shh[j] : (unsigned short)0xFC00u;
        __syncthreads();

        __half2 ha2[ROWS_R], cc2[ROWS_R];
#pragma unroll
        for (int r = 0; r < ROWS_R; r++) {
            int e = ch * CE + t + r * THREADS;
            unsigned short hb = (e < nev) ? g_evh[e] : (unsigned short)0x7C00u;
            ha2[r] = __half2half2(__ushort_as_half(hb));
            cc2[r] = __float2half2_rn(0.0f);
        }
        const __half2* sp = (const __half2*)s_h32;
#pragma unroll 8
        for (int jj = 0; jj < TJ / 2; jj++) {
            __half2 hb2 = sp[jj];
#pragma unroll
            for (int r = 0; r < ROWS_R; r++)
                cc2[r] = __hadd2(cc2[r], __hge2(hb2, ha2[r]));
        }
        float cf = 0.0f;
#pragma unroll
        for (int r = 0; r < ROWS_R; r++)
            cf += __low2float(cc2[r]) + __high2float(cc2[r]);   // <=128/half: exact
        cc += (unsigned int)cf;
    }

    // boundary slivers: event e covers j in [s_e, T_chunk), one warp/event
    {
        const int nw = THREADS / 32;
        const int gw = blk * nw + (t >> 5), lane = t & 31;
        for (int e = gw; e < nev; e += GRID * nw) {
            const int ch = e / CE;
            const int elast = min(ch * CE + CE, nev) - 1;
            const int T  = (int)g_evs[elast];
            const int s0 = (int)g_evs[e];
            const __half ha = __ushort_as_half(g_evh[e]);
            unsigned c = 0u;
            for (int j = s0 + lane; j < T; j += 32)
                if (__hge(__ushort_as_half(g_shh[j]), ha)) c++;
#pragma unroll
            for (int o = 16; o > 0; o >>= 1) c += __shfl_down_sync(0xFFFFFFFFu, c, o);
            if (lane == 0) cc += c;
        }
    }

    // zero hist/cnt for next graph replay (no longer read this run)
    if (gid < NBINS) { g_hist[gid] = 0u; g_cnt[gid] = 0u; }

    // ---- block reduce cc + arrival / finalize -----------------------------
#pragma unroll
    for (int o = 16; o > 0; o >>= 1) cc += __shfl_down_sync(0xFFFFFFFFu, cc, o);
    if ((t & 31) == 0) s_red[t >> 5] = cc;
    __syncthreads();
    if (t == 0) {
        unsigned bc = 0u;
#pragma unroll
        for (int i = 0; i < THREADS / 32; i++) bc += s_red[i];
        if (bc) atomicAdd(&g_acc, ((unsigned long long)bc) << 32);
        __threadfence();
        unsigned a = atomicAdd(&g_done2, 1u) + 1u;
        if (a == GRID) {
            unsigned long long acc = *((volatile unsigned long long*)&g_acc);
            out[0] = (float)(unsigned)(acc >> 32) / (float)(unsigned)(acc & 0xFFFFFFFFull);
            g_acc = 0ull; g_done2 = 0u; g_nev = 0;
            g_bar[0] = 0u; g_bar[1] = 0u; g_bar[2] = 0u;
        }
    }
}

extern "C" void kernel_launch(void* const* d_in, const int* in_sizes, int n_in,
                              void* d_out, int out_size) {
    const float* y  = (const float*)d_in[0];
    const float* yh = (const float*)d_in[1];
    const int*   st = (const int*)d_in[2];
    float* out = (float*)d_out;

    int n = in_sizes[0];  // 16384
    cindex_sort2_kernel<<<GRID, THREADS>>>(y, yh, st, out, n);
}